// round 1
// baseline (speedup 1.0000x reference)
#include <cuda_runtime.h>

// Problem constants (fixed shapes from reference)
#define NN   2048     // nodes
#define BB   64       // batch
#define CC   64       // dim_in == dim_out
#define ED   10       // embed dim
#define BC   4096     // BB*CC
#define KCH  3        // cheb_k

// ---------------- scratch (static device globals; no runtime allocation) ----
__device__ float g_A  [(size_t)NN * NN];   // softmax(relu(E E^T))
__device__ float g_T2 [(size_t)NN * NN];   // 2 A A - I
__device__ float g_xT [(size_t)NN * BC];   // x transposed to [N, B*C]
__device__ float g_Xg1[(size_t)NN * BC];   // A  @ xT
__device__ float g_Xg2[(size_t)NN * BC];   // T2 @ xT
__device__ float g_W  [(size_t)NN * KCH * CC * CC]; // per-node weights [N,3,64,64]

// ---------------- A = softmax(relu(E E^T)), one block per row --------------
__global__ __launch_bounds__(256) void supports_kernel(const float* __restrict__ E)
{
    int n   = blockIdx.x;
    int tid = threadIdx.x;

    float en[ED];
#pragma unroll
    for (int d = 0; d < ED; d++) en[d] = E[n * ED + d];

    float v[8];
    float mx = 0.0f;  // relu output >= 0, diagonal > 0
#pragma unroll
    for (int j = 0; j < 8; j++) {
        int m = j * 256 + tid;
        float dot = 0.f;
#pragma unroll
        for (int d = 0; d < ED; d++) dot += en[d] * __ldg(&E[m * ED + d]);
        v[j] = fmaxf(dot, 0.f);
        mx   = fmaxf(mx, v[j]);
    }

    __shared__ float red[256];
    red[tid] = mx; __syncthreads();
    for (int s = 128; s > 0; s >>= 1) {
        if (tid < s) red[tid] = fmaxf(red[tid], red[tid + s]);
        __syncthreads();
    }
    mx = red[0]; __syncthreads();

    float sum = 0.f;
#pragma unroll
    for (int j = 0; j < 8; j++) { v[j] = expf(v[j] - mx); sum += v[j]; }

    red[tid] = sum; __syncthreads();
    for (int s = 128; s > 0; s >>= 1) {
        if (tid < s) red[tid] += red[tid + s];
        __syncthreads();
    }
    float inv = 1.0f / red[0];

#pragma unroll
    for (int j = 0; j < 8; j++)
        g_A[(size_t)n * NN + j * 256 + tid] = v[j] * inv;
}

// ---------------- xT[n, b*64+c] = x[b, n, c] --------------------------------
__global__ __launch_bounds__(256) void transpose_kernel(const float* __restrict__ x)
{
    int t  = blockIdx.x * blockDim.x + threadIdx.x;  // over B*N*16 float4s
    int c4 = t & 15;
    int n  = (t >> 4) & (NN - 1);
    int b  = t >> 15;
    float4 v = *(const float4*)&x[((size_t)b * NN + n) * CC + c4 * 4];
    *(float4*)&g_xT[(size_t)n * BC + b * CC + c4 * 4] = v;
}

// ---------------- W[n, k, i, o] = sum_d E[n,d] Wp[d,k,i,o] ------------------
__global__ __launch_bounds__(256) void weights_kernel(const float* __restrict__ E,
                                                      const float* __restrict__ Wp)
{
    int t  = blockIdx.x * blockDim.x + threadIdx.x;  // over N*3072 float4s
    int j4 = t % 3072;
    int n  = t / 3072;
    float4 acc = make_float4(0.f, 0.f, 0.f, 0.f);
#pragma unroll
    for (int d = 0; d < ED; d++) {
        float  e = __ldg(&E[n * ED + d]);
        float4 w = *(const float4*)&Wp[(size_t)d * 12288 + j4 * 4];
        acc.x += e * w.x; acc.y += e * w.y; acc.z += e * w.z; acc.w += e * w.w;
    }
    *(float4*)&g_W[(size_t)n * 12288 + j4 * 4] = acc;
}

// ---------------- classic 128x128x8 register-tiled SGEMM -------------------
// C[M,N] = alpha * A[M,K] @ B[K,N]  (- I if subI)
__global__ __launch_bounds__(256) void sgemm_kernel(const float* __restrict__ A,
                                                    const float* __restrict__ B,
                                                    float* __restrict__ C,
                                                    int M, int N, int K,
                                                    float alpha, int subI)
{
    __shared__ float As[8][128];
    __shared__ float Bs[8][128];

    int tid = threadIdx.x;
    int bx  = blockIdx.x, by = blockIdx.y;

    int arow = tid >> 1, acol = (tid & 1) * 4;      // A tile 128x8
    int brow = tid >> 5, bcol = (tid & 31) * 4;     // B tile 8x128

    const float* Ap = A + ((size_t)(by * 128 + arow)) * K + acol;
    const float* Bp = B + (size_t)brow * N + bx * 128 + bcol;

    int tx = tid & 15, ty = tid >> 4;               // 16x16 thread grid, 8x8 each

    float acc[8][8];
#pragma unroll
    for (int i = 0; i < 8; i++)
#pragma unroll
        for (int j = 0; j < 8; j++) acc[i][j] = 0.f;

    for (int k0 = 0; k0 < K; k0 += 8) {
        float4 a4 = *(const float4*)Ap;  Ap += 8;
        float4 b4 = *(const float4*)Bp;  Bp += (size_t)8 * N;

        As[acol + 0][arow] = a4.x;
        As[acol + 1][arow] = a4.y;
        As[acol + 2][arow] = a4.z;
        As[acol + 3][arow] = a4.w;
        *(float4*)&Bs[brow][bcol] = b4;
        __syncthreads();

        float ra[8], rb[8];
#pragma unroll
        for (int kk = 0; kk < 8; kk++) {
            *(float4*)&ra[0] = *(const float4*)&As[kk][ty * 8];
            *(float4*)&ra[4] = *(const float4*)&As[kk][ty * 8 + 4];
            *(float4*)&rb[0] = *(const float4*)&Bs[kk][tx * 8];
            *(float4*)&rb[4] = *(const float4*)&Bs[kk][tx * 8 + 4];
#pragma unroll
            for (int i = 0; i < 8; i++)
#pragma unroll
                for (int j = 0; j < 8; j++) acc[i][j] += ra[i] * rb[j];
        }
        __syncthreads();
    }

    int crow0 = by * 128 + ty * 8;
    int ccol0 = bx * 128 + tx * 8;
#pragma unroll
    for (int i = 0; i < 8; i++) {
        int row = crow0 + i;
#pragma unroll
        for (int j = 0; j < 8; j += 4) {
            float s[4];
#pragma unroll
            for (int t = 0; t < 4; t++) {
                s[t] = alpha * acc[i][j + t];
                if (subI && row == ccol0 + j + t) s[t] -= 1.0f;
            }
            float4 v = make_float4(s[0], s[1], s[2], s[3]);
            *(float4*)&C[(size_t)row * N + ccol0 + j] = v;
        }
    }
}

// ---------------- final: per node n, out[:,n,:] = sum_k Xg_k @ W_nk + bias --
__global__ __launch_bounds__(256) void final_kernel(const float* __restrict__ x,
                                                    const float* __restrict__ E,
                                                    const float* __restrict__ bp,
                                                    float* __restrict__ out)
{
    int n   = blockIdx.x;
    int tid = threadIdx.x;
    int tx  = tid & 15, ty = tid >> 4;   // 16x16 threads, 4x4 outputs each

    __shared__ float Xs[64][64];   // [b][i]
    __shared__ float Ws[64][64];   // [i][o]

    float acc[4][4];
#pragma unroll
    for (int r = 0; r < 4; r++)
#pragma unroll
        for (int c = 0; c < 4; c++) acc[r][c] = 0.f;

#pragma unroll
    for (int k = 0; k < KCH; k++) {
        // load Xg_k tile: k=0 is x itself (identity Chebyshev term)
        if (k == 0) {
#pragma unroll
            for (int t = 0; t < 4; t++) {
                int e  = tid + t * 256;
                int b  = e >> 4, i4 = e & 15;
                *(float4*)&Xs[b][i4 * 4] =
                    *(const float4*)&x[((size_t)b * NN + n) * CC + i4 * 4];
            }
        } else {
            const float* src = (k == 1 ? g_Xg1 : g_Xg2) + (size_t)n * BC;
#pragma unroll
            for (int t = 0; t < 4; t++) {
                int e = tid + t * 256;
                ((float4*)Xs)[e] = ((const float4*)src)[e];
            }
        }
        const float* wsrc = g_W + (size_t)n * 12288 + (size_t)k * 4096;
#pragma unroll
        for (int t = 0; t < 4; t++) {
            int e = tid + t * 256;
            ((float4*)Ws)[e] = ((const float4*)wsrc)[e];
        }
        __syncthreads();

#pragma unroll 8
        for (int i = 0; i < 64; i++) {
            float xr[4];
#pragma unroll
            for (int r = 0; r < 4; r++) xr[r] = Xs[ty * 4 + r][i];
            float4 wv = *(const float4*)&Ws[i][tx * 4];
#pragma unroll
            for (int r = 0; r < 4; r++) {
                acc[r][0] += xr[r] * wv.x;
                acc[r][1] += xr[r] * wv.y;
                acc[r][2] += xr[r] * wv.z;
                acc[r][3] += xr[r] * wv.w;
            }
        }
        __syncthreads();
    }

    // bias[n, o] = sum_d E[n,d] * bp[d, o]
    float bias[4] = {0.f, 0.f, 0.f, 0.f};
#pragma unroll
    for (int d = 0; d < ED; d++) {
        float e = __ldg(&E[n * ED + d]);
#pragma unroll
        for (int c = 0; c < 4; c++) bias[c] += e * __ldg(&bp[d * CC + tx * 4 + c]);
    }

#pragma unroll
    for (int r = 0; r < 4; r++) {
        int b = ty * 4 + r;
        float4 v = make_float4(acc[r][0] + bias[0], acc[r][1] + bias[1],
                               acc[r][2] + bias[2], acc[r][3] + bias[3]);
        *(float4*)&out[((size_t)b * NN + n) * CC + tx * 4] = v;
    }
}

// ---------------- launch ----------------------------------------------------
extern "C" void kernel_launch(void* const* d_in, const int* in_sizes, int n_in,
                              void* d_out, int out_size)
{
    const float* x  = (const float*)d_in[0];  // [64, 2048, 64]
    const float* E  = (const float*)d_in[1];  // [2048, 10]
    const float* Wp = (const float*)d_in[2];  // [10, 3, 64, 64]
    const float* bp = (const float*)d_in[3];  // [10, 64]
    float* out = (float*)d_out;               // [64, 2048, 64]

    float *pA, *pT2, *pxT, *pXg1, *pXg2;
    cudaGetSymbolAddress((void**)&pA,   g_A);
    cudaGetSymbolAddress((void**)&pT2,  g_T2);
    cudaGetSymbolAddress((void**)&pxT,  g_xT);
    cudaGetSymbolAddress((void**)&pXg1, g_Xg1);
    cudaGetSymbolAddress((void**)&pXg2, g_Xg2);

    // 1. adjacency
    supports_kernel<<<NN, 256>>>(E);
    // 2. xT (independent of 1)
    transpose_kernel<<<(BB * NN * 16) / 256, 256>>>(x);
    // 3. T2 = 2*A@A - I
    sgemm_kernel<<<dim3(NN / 128, NN / 128), 256>>>(pA, pA, pT2, NN, NN, NN, 2.0f, 1);
    // 4. Xg1 = A @ xT
    sgemm_kernel<<<dim3(BC / 128, NN / 128), 256>>>(pA, pxT, pXg1, NN, BC, NN, 1.0f, 0);
    // 5. Xg2 = T2 @ xT
    sgemm_kernel<<<dim3(BC / 128, NN / 128), 256>>>(pT2, pxT, pXg2, NN, BC, NN, 1.0f, 0);
    // 6. per-node weights (independent)
    weights_kernel<<<(NN * 3072) / 256, 256>>>(E, Wp);
    // 7. final contraction + bias
    final_kernel<<<NN, 256>>>(x, E, bp, out);
}

// round 3
// speedup vs baseline: 3.4945x; 3.4945x over previous
#include <cuda_runtime.h>
#include <cstdint>

// Problem constants
#define NN   2048
#define BB   64
#define CC   64
#define ED   10
#define BC   4096
#define KCH  3

// ---------------- scratch ----------------------------------------------------
__device__ float g_A  [(size_t)NN * NN];   // softmax(relu(E E^T)), tf32-rounded
__device__ float g_AT [(size_t)NN * NN];   // A^T (tf32-rounded by construction)
__device__ float g_T2 [(size_t)NN * NN];   // 2 A A - I, tf32-rounded on write
__device__ float g_xTT[(size_t)BC * NN];   // xTT[b*64+c][n] = x[b][n][c], tf32-rounded
__device__ float g_Xg1[(size_t)NN * BC];   // A  @ xT  (full fp32)
__device__ float g_Xg2[(size_t)NN * BC];   // T2 @ xT  (full fp32)
__device__ float g_W  [(size_t)NN * KCH * CC * CC];

// ---------------- helpers ------------------------------------------------
__device__ __forceinline__ uint32_t smem_u32(const void* p) {
    uint32_t a;
    asm("{ .reg .u64 t; cvta.to.shared.u64 t, %1; cvt.u32.u64 %0, t; }" : "=r"(a) : "l"(p));
    return a;
}
__device__ __forceinline__ uint32_t f2tf32(float f) {
    uint32_t r;
    asm("cvt.rna.tf32.f32 %0, %1;" : "=r"(r) : "f"(f));
    return r;
}
__device__ __forceinline__ float tf32r(float f) { return __uint_as_float(f2tf32(f)); }

#define SWZ128(o) ((o) ^ (((o) >> 3) & 0x70))

__device__ __forceinline__ void cp16(uint32_t dst, const void* src) {
    asm volatile("cp.async.cg.shared.global [%0], [%1], 16;" :: "r"(dst), "l"(src) : "memory");
}
__device__ __forceinline__ void mma8(float* d, const uint32_t* a, const uint32_t* b) {
    asm volatile("mma.sync.aligned.m16n8k8.row.col.f32.tf32.tf32.f32 "
        "{%0,%1,%2,%3}, {%4,%5,%6,%7}, {%8,%9}, {%0,%1,%2,%3};"
        : "+f"(d[0]), "+f"(d[1]), "+f"(d[2]), "+f"(d[3])
        : "r"(a[0]), "r"(a[1]), "r"(a[2]), "r"(a[3]), "r"(b[0]), "r"(b[1]));
}

// ---------------- tf32 mma.sync GEMM: C = alpha * Aop @ Bop^T (- I) ---------
// Aop: [M,2048] row-major.  Bop: [Ncols,2048] row-major (used as B^T).
// CTA tile 128x128, warp tile 64x32, K-chunk 32, cp.async double buffer.
__global__ __launch_bounds__(256, 2)
void gemm_mma(const float* __restrict__ Aop, const float* __restrict__ Bop,
              float* __restrict__ C, int ldcN, float alpha, int subI, int roundOut)
{
    extern __shared__ char smem[];
    uint32_t sbase = smem_u32(smem);
    const uint32_t aoff[2] = {0u, 32768u};
    const uint32_t boff[2] = {16384u, 49152u};

    int tid = threadIdx.x, wid = tid >> 5, lid = tid & 31;
    int m0 = blockIdx.y * 128, n0 = blockIdx.x * 128;

    // loader mapping: thread -> (row ldr + 32*i, k-quad ldc4)
    int ldr = tid >> 3, ldc4 = tid & 7;
    uint32_t swz_ld = (uint32_t)(ldr * 128 + ((ldc4 * 16) ^ ((ldr & 7) * 16)));
    const float* ga = Aop + (size_t)(m0 + ldr) * NN + ldc4 * 4;
    const float* gb = Bop + (size_t)(n0 + ldr) * NN + ldc4 * 4;

#define LOAD_CHUNK(kc, buf) do { \
    int _k0 = (kc) * 32; \
    uint32_t _as = sbase + aoff[buf] + swz_ld; \
    uint32_t _bs = sbase + boff[buf] + swz_ld; \
    _Pragma("unroll") for (int i = 0; i < 4; i++) { \
        cp16(_as + (uint32_t)i * 4096u, ga + (size_t)i * 32 * NN + _k0); \
        cp16(_bs + (uint32_t)i * 4096u, gb + (size_t)i * 32 * NN + _k0); \
    } \
    asm volatile("cp.async.commit_group;" ::: "memory"); \
} while (0)

    // compute mapping
    int wm = wid & 1, wn = wid >> 1;          // 2 x 4 warps
    int lane4 = lid & 3, lgrp = lid >> 2;
    uint32_t amsk = (uint32_t)(lgrp * 16);
    uint32_t arow = (uint32_t)((wm * 64 + lgrp) * 128 + lane4 * 4);
    uint32_t brow = (uint32_t)((wn * 32 + lgrp) * 128 + lane4 * 4);

    float acc[4][4][4];
#pragma unroll
    for (int mt = 0; mt < 4; mt++)
#pragma unroll
        for (int nt = 0; nt < 4; nt++)
#pragma unroll
            for (int c = 0; c < 4; c++) acc[mt][nt][c] = 0.f;

    LOAD_CHUNK(0, 0);
    LOAD_CHUNK(1, 1);

    for (int kc = 0; kc < 64; kc++) {
        asm volatile("cp.async.wait_group 1;" ::: "memory");
        __syncthreads();

        uint32_t ab = sbase + aoff[kc & 1];
        uint32_t bb = sbase + boff[kc & 1];
#pragma unroll
        for (int kk = 0; kk < 4; kk++) {
            uint32_t a[4][4], b[4][2];
#pragma unroll
            for (int mt = 0; mt < 4; mt++)
#pragma unroll
                for (int j = 0; j < 4; j++) {
                    uint32_t ad = ab + arow + (uint32_t)(mt * 2048 + (j & 1) * 1024)
                                + (((uint32_t)(kk * 32 + (j >> 1) * 16)) ^ amsk);
                    asm volatile("ld.shared.b32 %0, [%1];" : "=r"(a[mt][j]) : "r"(ad));
                }
#pragma unroll
            for (int nt = 0; nt < 4; nt++)
#pragma unroll
                for (int j = 0; j < 2; j++) {
                    uint32_t bd = bb + brow + (uint32_t)(nt * 1024)
                                + (((uint32_t)(kk * 32 + j * 16)) ^ amsk);
                    asm volatile("ld.shared.b32 %0, [%1];" : "=r"(b[nt][j]) : "r"(bd));
                }
#pragma unroll
            for (int mt = 0; mt < 4; mt++)
#pragma unroll
                for (int nt = 0; nt < 4; nt++)
                    mma8(acc[mt][nt], a[mt], b[nt]);
        }
        __syncthreads();

        if (kc + 2 < 64) LOAD_CHUNK(kc + 2, kc & 1);
        else asm volatile("cp.async.commit_group;" ::: "memory");
    }
#undef LOAD_CHUNK

    // epilogue
    int row0 = m0 + wm * 64;
    int col0 = n0 + wn * 32 + lane4 * 2;
#pragma unroll
    for (int mt = 0; mt < 4; mt++) {
#pragma unroll
        for (int nt = 0; nt < 4; nt++) {
            int r = row0 + mt * 16 + lgrp;
            int c = col0 + nt * 8;
            float v0 = alpha * acc[mt][nt][0];
            float v1 = alpha * acc[mt][nt][1];
            float v2 = alpha * acc[mt][nt][2];
            float v3 = alpha * acc[mt][nt][3];
            if (subI) {
                if (r == c)         v0 -= 1.f;
                if (r == c + 1)     v1 -= 1.f;
                if (r + 8 == c)     v2 -= 1.f;
                if (r + 8 == c + 1) v3 -= 1.f;
            }
            if (roundOut) {
                v0 = tf32r(v0); v1 = tf32r(v1); v2 = tf32r(v2); v3 = tf32r(v3);
            }
            *(float2*)&C[(size_t)r * ldcN + c]       = make_float2(v0, v1);
            *(float2*)&C[(size_t)(r + 8) * ldcN + c] = make_float2(v2, v3);
        }
    }
}

// ---------------- A = softmax(relu(E E^T)), tf32-rounded output -------------
__global__ __launch_bounds__(256) void supports_kernel(const float* __restrict__ E)
{
    int n = blockIdx.x, tid = threadIdx.x;
    float en[ED];
#pragma unroll
    for (int d = 0; d < ED; d++) en[d] = E[n * ED + d];

    float v[8], mx = 0.0f;
#pragma unroll
    for (int j = 0; j < 8; j++) {
        int m = j * 256 + tid;
        float dot = 0.f;
#pragma unroll
        for (int d = 0; d < ED; d++) dot += en[d] * __ldg(&E[m * ED + d]);
        v[j] = fmaxf(dot, 0.f);
        mx = fmaxf(mx, v[j]);
    }
    __shared__ float red[256];
    red[tid] = mx; __syncthreads();
    for (int s = 128; s > 0; s >>= 1) {
        if (tid < s) red[tid] = fmaxf(red[tid], red[tid + s]);
        __syncthreads();
    }
    mx = red[0]; __syncthreads();
    float sum = 0.f;
#pragma unroll
    for (int j = 0; j < 8; j++) { v[j] = expf(v[j] - mx); sum += v[j]; }
    red[tid] = sum; __syncthreads();
    for (int s = 128; s > 0; s >>= 1) {
        if (tid < s) red[tid] += red[tid + s];
        __syncthreads();
    }
    float inv = 1.0f / red[0];
#pragma unroll
    for (int j = 0; j < 8; j++)
        g_A[(size_t)n * NN + j * 256 + tid] = tf32r(v[j] * inv);
}

// ---------------- AT = A^T ---------------------------------------------------
__global__ __launch_bounds__(256) void transposeA_kernel()
{
    __shared__ float t[32][33];
    int tx = threadIdx.x, ty = threadIdx.y;
    int bx = blockIdx.x * 32, by = blockIdx.y * 32;
#pragma unroll
    for (int i = 0; i < 32; i += 8)
        t[ty + i][tx] = g_A[(size_t)(by + ty + i) * NN + bx + tx];
    __syncthreads();
#pragma unroll
    for (int i = 0; i < 32; i += 8)
        g_AT[(size_t)(bx + ty + i) * NN + by + tx] = t[tx][ty + i];
}

// ---------------- xTT[b*64+c][n] = x[b][n][c] (tf32-rounded) ----------------
__global__ __launch_bounds__(256) void transpose_x_kernel(const float* __restrict__ x)
{
    __shared__ float t[32][33];
    int tx = threadIdx.x, ty = threadIdx.y;
    int b = blockIdx.z;
    int n0 = blockIdx.x * 32, c0 = blockIdx.y * 32;
    const float* S = x + (size_t)b * NN * CC;
#pragma unroll
    for (int i = 0; i < 32; i += 8)
        t[ty + i][tx] = S[(size_t)(n0 + ty + i) * CC + c0 + tx];
    __syncthreads();
    float* D = g_xTT + (size_t)b * CC * NN;
#pragma unroll
    for (int i = 0; i < 32; i += 8)
        D[(size_t)(c0 + ty + i) * NN + n0 + tx] = tf32r(t[tx][ty + i]);
}

// ---------------- W[n,k,i,o] = sum_d E[n,d] Wp[d,k,i,o] ----------------------
__global__ __launch_bounds__(256) void weights_kernel(const float* __restrict__ E,
                                                      const float* __restrict__ Wp)
{
    int t = blockIdx.x * blockDim.x + threadIdx.x;
    int j4 = t % 3072;
    int n  = t / 3072;
    float4 acc = make_float4(0.f, 0.f, 0.f, 0.f);
#pragma unroll
    for (int d = 0; d < ED; d++) {
        float  e = __ldg(&E[n * ED + d]);
        float4 w = *(const float4*)&Wp[(size_t)d * 12288 + j4 * 4];
        acc.x += e * w.x; acc.y += e * w.y; acc.z += e * w.z; acc.w += e * w.w;
    }
    *(float4*)&g_W[(size_t)n * 12288 + j4 * 4] = acc;
}

// ---------------- final: out[:,n,:] = sum_k Xg_k @ W_nk + bias ---------------
__global__ __launch_bounds__(256) void final_kernel(const float* __restrict__ x,
                                                    const float* __restrict__ E,
                                                    const float* __restrict__ bp,
                                                    float* __restrict__ out)
{
    int n = blockIdx.x, tid = threadIdx.x;
    int tx = tid & 15, ty = tid >> 4;

    __shared__ float Xs[64][64];
    __shared__ float Ws[64][64];

    float acc[4][4];
#pragma unroll
    for (int r = 0; r < 4; r++)
#pragma unroll
        for (int c = 0; c < 4; c++) acc[r][c] = 0.f;

#pragma unroll
    for (int k = 0; k < KCH; k++) {
        if (k == 0) {
#pragma unroll
            for (int t = 0; t < 4; t++) {
                int e = tid + t * 256;
                int b = e >> 4, i4 = e & 15;
                *(float4*)&Xs[b][i4 * 4] =
                    *(const float4*)&x[((size_t)b * NN + n) * CC + i4 * 4];
            }
        } else {
            const float* src = (k == 1 ? g_Xg1 : g_Xg2) + (size_t)n * BC;
#pragma unroll
            for (int t = 0; t < 4; t++) {
                int e = tid + t * 256;
                ((float4*)Xs)[e] = ((const float4*)src)[e];
            }
        }
        const float* wsrc = g_W + (size_t)n * 12288 + (size_t)k * 4096;
#pragma unroll
        for (int t = 0; t < 4; t++) {
            int e = tid + t * 256;
            ((float4*)Ws)[e] = ((const float4*)wsrc)[e];
        }
        __syncthreads();

#pragma unroll 8
        for (int i = 0; i < 64; i++) {
            float xr[4];
#pragma unroll
            for (int r = 0; r < 4; r++) xr[r] = Xs[ty * 4 + r][i];
            float4 wv = *(const float4*)&Ws[i][tx * 4];
#pragma unroll
            for (int r = 0; r < 4; r++) {
                acc[r][0] += xr[r] * wv.x;
                acc[r][1] += xr[r] * wv.y;
                acc[r][2] += xr[r] * wv.z;
                acc[r][3] += xr[r] * wv.w;
            }
        }
        __syncthreads();
    }

    float bias[4] = {0.f, 0.f, 0.f, 0.f};
#pragma unroll
    for (int d = 0; d < ED; d++) {
        float e = __ldg(&E[n * ED + d]);
#pragma unroll
        for (int c = 0; c < 4; c++) bias[c] += e * __ldg(&bp[d * CC + tx * 4 + c]);
    }

#pragma unroll
    for (int r = 0; r < 4; r++) {
        int b = ty * 4 + r;
        float4 v = make_float4(acc[r][0] + bias[0], acc[r][1] + bias[1],
                               acc[r][2] + bias[2], acc[r][3] + bias[3]);
        *(float4*)&out[((size_t)b * NN + n) * CC + tx * 4] = v;
    }
}

// ---------------- launch ----------------------------------------------------
#define GEMM_SMEM 65536

extern "C" void kernel_launch(void* const* d_in, const int* in_sizes, int n_in,
                              void* d_out, int out_size)
{
    const float* x  = (const float*)d_in[0];
    const float* E  = (const float*)d_in[1];
    const float* Wp = (const float*)d_in[2];
    const float* bp = (const float*)d_in[3];
    float* out = (float*)d_out;

    float *pA, *pAT, *pT2, *pxTT, *pXg1, *pXg2;
    cudaGetSymbolAddress((void**)&pA,   g_A);
    cudaGetSymbolAddress((void**)&pAT,  g_AT);
    cudaGetSymbolAddress((void**)&pT2,  g_T2);
    cudaGetSymbolAddress((void**)&pxTT, g_xTT);
    cudaGetSymbolAddress((void**)&pXg1, g_Xg1);
    cudaGetSymbolAddress((void**)&pXg2, g_Xg2);

    static bool attr_set = false;
    if (!attr_set) {
        cudaFuncSetAttribute(gemm_mma, cudaFuncAttributeMaxDynamicSharedMemorySize, GEMM_SMEM);
        attr_set = true;
    }

    // 1. adjacency (tf32-rounded)
    supports_kernel<<<NN, 256>>>(E);
    // 2. transposes
    transposeA_kernel<<<dim3(64, 64), dim3(32, 8)>>>();
    transpose_x_kernel<<<dim3(64, 2, 64), dim3(32, 8)>>>(x);
    // 3. T2 = 2*A@A - I   (B operand = A^T), tf32-rounded output
    gemm_mma<<<dim3(NN / 128, NN / 128), 256, GEMM_SMEM>>>(pA, pAT, pT2, NN, 2.0f, 1, 1);
    // 4. Xg1 = A @ xT     (B operand = xTT)
    gemm_mma<<<dim3(BC / 128, NN / 128), 256, GEMM_SMEM>>>(pA, pxTT, pXg1, BC, 1.0f, 0, 0);
    // 5. Xg2 = T2 @ xT
    gemm_mma<<<dim3(BC / 128, NN / 128), 256, GEMM_SMEM>>>(pT2, pxTT, pXg2, BC, 1.0f, 0, 0);
    // 6. per-node weights
    weights_kernel<<<(NN * 3072) / 256, 256>>>(E, Wp);
    // 7. final contraction + bias
    final_kernel<<<NN, 256>>>(x, E, bp, out);
}

// round 4
// speedup vs baseline: 3.7501x; 1.0731x over previous
#include <cuda_runtime.h>
#include <cstdint>

// Problem constants
#define NN   2048
#define BB   64
#define CC   64
#define ED   10
#define BC   4096
#define KCH  3

// ---------------- scratch ----------------------------------------------------
__device__ float g_A  [(size_t)NN * NN];
__device__ float g_AT [(size_t)NN * NN];
__device__ float g_T2 [(size_t)NN * NN];
__device__ float g_xTT[(size_t)BC * NN];
__device__ float g_Xg1[(size_t)NN * BC];
__device__ float g_Xg2[(size_t)NN * BC];
__device__ float g_W  [(size_t)NN * KCH * CC * CC];

// ---------------- helpers ------------------------------------------------
__device__ __forceinline__ uint32_t smem_u32(const void* p) {
    uint32_t a;
    asm("{ .reg .u64 t; cvta.to.shared.u64 t, %1; cvt.u32.u64 %0, t; }" : "=r"(a) : "l"(p));
    return a;
}
__device__ __forceinline__ uint32_t f2tf32(float f) {
    uint32_t r;
    asm("cvt.rna.tf32.f32 %0, %1;" : "=r"(r) : "f"(f));
    return r;
}
__device__ __forceinline__ float tf32r(float f) { return __uint_as_float(f2tf32(f)); }

__device__ __forceinline__ void cp16(uint32_t dst, const void* src) {
    asm volatile("cp.async.cg.shared.global [%0], [%1], 16;" :: "r"(dst), "l"(src) : "memory");
}
__device__ __forceinline__ void mma8(float* d, const uint32_t* a, const uint32_t* b) {
    asm volatile("mma.sync.aligned.m16n8k8.row.col.f32.tf32.tf32.f32 "
        "{%0,%1,%2,%3}, {%4,%5,%6,%7}, {%8,%9}, {%0,%1,%2,%3};"
        : "+f"(d[0]), "+f"(d[1]), "+f"(d[2]), "+f"(d[3])
        : "r"(a[0]), "r"(a[1]), "r"(a[2]), "r"(a[3]), "r"(b[0]), "r"(b[1]));
}
__device__ __forceinline__ void ldmat4(uint32_t* r, uint32_t addr) {
    asm volatile("ldmatrix.sync.aligned.m8n8.x4.shared.b16 {%0,%1,%2,%3}, [%4];"
        : "=r"(r[0]), "=r"(r[1]), "=r"(r[2]), "=r"(r[3]) : "r"(addr));
}

// ---------------- tf32 mma.sync GEMM: C = alpha * Aop @ Bop^T (- I) ---------
// Aop: [M,2048] row-major.  Bop: [Ncols,2048] row-major (used as B^T).
// CTA tile 128x128, warp tile 64x32, K-chunk 32, cp.async double buffer,
// ldmatrix fragment feeds.
__global__ __launch_bounds__(256, 2)
void gemm_mma(const float* __restrict__ Aop, const float* __restrict__ Bop,
              float* __restrict__ C, int ldcN, float alpha, int subI, int roundOut)
{
    extern __shared__ char smem[];
    uint32_t sbase = smem_u32(smem);
    const uint32_t aoff[2] = {0u, 32768u};
    const uint32_t boff[2] = {16384u, 49152u};

    int tid = threadIdx.x, wid = tid >> 5, lid = tid & 31;
    int m0 = blockIdx.y * 128, n0 = blockIdx.x * 128;

    // ---- loader mapping: thread -> (row ldr + 32*i, 16B k-group ldc4) ----
    int ldr = tid >> 3, ldc4 = tid & 7;
    uint32_t swz_ld = (uint32_t)(ldr * 128 + ((ldc4 * 16) ^ ((ldr & 7) * 16)));
    const float* ga = Aop + (size_t)(m0 + ldr) * NN + ldc4 * 4;
    const float* gb = Bop + (size_t)(n0 + ldr) * NN + ldc4 * 4;

#define LOAD_CHUNK(kc, buf) do { \
    int _k0 = (kc) * 32; \
    uint32_t _as = sbase + aoff[buf] + swz_ld; \
    uint32_t _bs = sbase + boff[buf] + swz_ld; \
    _Pragma("unroll") for (int i = 0; i < 4; i++) { \
        cp16(_as + (uint32_t)i * 4096u, ga + (size_t)i * 32 * NN + _k0); \
        cp16(_bs + (uint32_t)i * 4096u, gb + (size_t)i * 32 * NN + _k0); \
    } \
    asm volatile("cp.async.commit_group;" ::: "memory"); \
} while (0)

    // ---- compute mapping (2 x 4 warps of 64x32) ----
    int wm = wid & 1, wn = wid >> 1;
    int lane4 = lid & 3, lgrp = lid >> 2;
    int t7 = lid & 7;
    uint32_t swzmask = (uint32_t)(t7 * 16);

    // A ldmatrix thread->row: tiles [m0-7,klo][m8-15,klo][m0-7,khi][m8-15,khi]
    uint32_t a_rowbase = (uint32_t)((wm * 64 + t7 + (((lid >> 3) & 1) << 3)) * 128);
    uint32_t a_khoff   = (uint32_t)(((lid >> 4) & 1) * 16);
    // B ldmatrix thread->row: tiles [n0-7,klo][n0-7,khi][n8-15,klo][n8-15,khi]
    uint32_t b_rowbase = (uint32_t)((wn * 32 + t7 + (((lid >> 4) & 1) << 3)) * 128);
    uint32_t b_khoff   = (uint32_t)(((lid >> 3) & 1) * 16);

    float acc[4][4][4];
#pragma unroll
    for (int mt = 0; mt < 4; mt++)
#pragma unroll
        for (int nt = 0; nt < 4; nt++)
#pragma unroll
            for (int c = 0; c < 4; c++) acc[mt][nt][c] = 0.f;

    LOAD_CHUNK(0, 0);
    LOAD_CHUNK(1, 1);

    for (int kc = 0; kc < 64; kc++) {
        asm volatile("cp.async.wait_group 1;" ::: "memory");
        __syncthreads();

        uint32_t ab = sbase + aoff[kc & 1];
        uint32_t bb = sbase + boff[kc & 1];
#pragma unroll
        for (int kk = 0; kk < 4; kk++) {
            uint32_t a[4][4], bfr[2][4];
            uint32_t a_k = ((uint32_t)(kk * 32) + a_khoff) ^ swzmask;
            uint32_t b_k = ((uint32_t)(kk * 32) + b_khoff) ^ swzmask;
#pragma unroll
            for (int mt = 0; mt < 4; mt++)
                ldmat4(a[mt], ab + a_rowbase + (uint32_t)(mt * 2048) + a_k);
#pragma unroll
            for (int np = 0; np < 2; np++)
                ldmat4(bfr[np], bb + b_rowbase + (uint32_t)(np * 2048) + b_k);
#pragma unroll
            for (int mt = 0; mt < 4; mt++)
#pragma unroll
                for (int nt = 0; nt < 4; nt++)
                    mma8(acc[mt][nt], a[mt], &bfr[nt >> 1][(nt & 1) * 2]);
        }
        __syncthreads();

        if (kc + 2 < 64) LOAD_CHUNK(kc + 2, kc & 1);
        else asm volatile("cp.async.commit_group;" ::: "memory");
    }
#undef LOAD_CHUNK

    // epilogue (fragment layout: rows lgrp/+8, cols lane4*2)
    int row0 = m0 + wm * 64;
    int col0 = n0 + wn * 32 + lane4 * 2;
#pragma unroll
    for (int mt = 0; mt < 4; mt++) {
#pragma unroll
        for (int nt = 0; nt < 4; nt++) {
            int r = row0 + mt * 16 + lgrp;
            int c = col0 + nt * 8;
            float v0 = alpha * acc[mt][nt][0];
            float v1 = alpha * acc[mt][nt][1];
            float v2 = alpha * acc[mt][nt][2];
            float v3 = alpha * acc[mt][nt][3];
            if (subI) {
                if (r == c)         v0 -= 1.f;
                if (r == c + 1)     v1 -= 1.f;
                if (r + 8 == c)     v2 -= 1.f;
                if (r + 8 == c + 1) v3 -= 1.f;
            }
            if (roundOut) {
                v0 = tf32r(v0); v1 = tf32r(v1); v2 = tf32r(v2); v3 = tf32r(v3);
            }
            *(float2*)&C[(size_t)r * ldcN + c]       = make_float2(v0, v1);
            *(float2*)&C[(size_t)(r + 8) * ldcN + c] = make_float2(v2, v3);
        }
    }
}

// ---------------- A = softmax(relu(E E^T)), tf32-rounded output -------------
__global__ __launch_bounds__(256) void supports_kernel(const float* __restrict__ E)
{
    int n = blockIdx.x, tid = threadIdx.x;
    float en[ED];
#pragma unroll
    for (int d = 0; d < ED; d++) en[d] = E[n * ED + d];

    float v[8], mx = 0.0f;
#pragma unroll
    for (int j = 0; j < 8; j++) {
        int m = j * 256 + tid;
        float dot = 0.f;
#pragma unroll
        for (int d = 0; d < ED; d++) dot += en[d] * __ldg(&E[m * ED + d]);
        v[j] = fmaxf(dot, 0.f);
        mx = fmaxf(mx, v[j]);
    }
    __shared__ float red[256];
    red[tid] = mx; __syncthreads();
    for (int s = 128; s > 0; s >>= 1) {
        if (tid < s) red[tid] = fmaxf(red[tid], red[tid + s]);
        __syncthreads();
    }
    mx = red[0]; __syncthreads();
    float sum = 0.f;
#pragma unroll
    for (int j = 0; j < 8; j++) { v[j] = expf(v[j] - mx); sum += v[j]; }
    red[tid] = sum; __syncthreads();
    for (int s = 128; s > 0; s >>= 1) {
        if (tid < s) red[tid] += red[tid + s];
        __syncthreads();
    }
    float inv = 1.0f / red[0];
#pragma unroll
    for (int j = 0; j < 8; j++)
        g_A[(size_t)n * NN + j * 256 + tid] = tf32r(v[j] * inv);
}

// ---------------- AT = A^T ---------------------------------------------------
__global__ __launch_bounds__(256) void transposeA_kernel()
{
    __shared__ float t[32][33];
    int tx = threadIdx.x, ty = threadIdx.y;
    int bx = blockIdx.x * 32, by = blockIdx.y * 32;
#pragma unroll
    for (int i = 0; i < 32; i += 8)
        t[ty + i][tx] = g_A[(size_t)(by + ty + i) * NN + bx + tx];
    __syncthreads();
#pragma unroll
    for (int i = 0; i < 32; i += 8)
        g_AT[(size_t)(bx + ty + i) * NN + by + tx] = t[tx][ty + i];
}

// ---------------- xTT[b*64+c][n] = x[b][n][c] (tf32-rounded) ----------------
__global__ __launch_bounds__(256) void transpose_x_kernel(const float* __restrict__ x)
{
    __shared__ float t[32][33];
    int tx = threadIdx.x, ty = threadIdx.y;
    int b = blockIdx.z;
    int n0 = blockIdx.x * 32, c0 = blockIdx.y * 32;
    const float* S = x + (size_t)b * NN * CC;
#pragma unroll
    for (int i = 0; i < 32; i += 8)
        t[ty + i][tx] = S[(size_t)(n0 + ty + i) * CC + c0 + tx];
    __syncthreads();
    float* D = g_xTT + (size_t)b * CC * NN;
#pragma unroll
    for (int i = 0; i < 32; i += 8)
        D[(size_t)(c0 + ty + i) * NN + n0 + tx] = tf32r(t[tx][ty + i]);
}

// ---------------- W[n,k,i,o] = sum_d E[n,d] Wp[d,k,i,o] ----------------------
__global__ __launch_bounds__(256) void weights_kernel(const float* __restrict__ E,
                                                      const float* __restrict__ Wp)
{
    int t = blockIdx.x * blockDim.x + threadIdx.x;
    int j4 = t % 3072;
    int n  = t / 3072;
    float4 acc = make_float4(0.f, 0.f, 0.f, 0.f);
#pragma unroll
    for (int d = 0; d < ED; d++) {
        float  e = __ldg(&E[n * ED + d]);
        float4 w = *(const float4*)&Wp[(size_t)d * 12288 + j4 * 4];
        acc.x += e * w.x; acc.y += e * w.y; acc.z += e * w.z; acc.w += e * w.w;
    }
    *(float4*)&g_W[(size_t)n * 12288 + j4 * 4] = acc;
}

// ---------------- final: out[:,n,:] = sum_k Xg_k @ W_nk + bias ---------------
__global__ __launch_bounds__(256) void final_kernel(const float* __restrict__ x,
                                                    const float* __restrict__ E,
                                                    const float* __restrict__ bp,
                                                    float* __restrict__ out)
{
    int n = blockIdx.x, tid = threadIdx.x;
    int tx = tid & 15, ty = tid >> 4;

    __shared__ float Xs[64][64];
    __shared__ float Ws[64][64];

    float acc[4][4];
#pragma unroll
    for (int r = 0; r < 4; r++)
#pragma unroll
        for (int c = 0; c < 4; c++) acc[r][c] = 0.f;

#pragma unroll
    for (int k = 0; k < KCH; k++) {
        if (k == 0) {
#pragma unroll
            for (int t = 0; t < 4; t++) {
                int e = tid + t * 256;
                int b = e >> 4, i4 = e & 15;
                *(float4*)&Xs[b][i4 * 4] =
                    *(const float4*)&x[((size_t)b * NN + n) * CC + i4 * 4];
            }
        } else {
            const float* src = (k == 1 ? g_Xg1 : g_Xg2) + (size_t)n * BC;
#pragma unroll
            for (int t = 0; t < 4; t++) {
                int e = tid + t * 256;
                ((float4*)Xs)[e] = ((const float4*)src)[e];
            }
        }
        const float* wsrc = g_W + (size_t)n * 12288 + (size_t)k * 4096;
#pragma unroll
        for (int t = 0; t < 4; t++) {
            int e = tid + t * 256;
            ((float4*)Ws)[e] = ((const float4*)wsrc)[e];
        }
        __syncthreads();

#pragma unroll 8
        for (int i = 0; i < 64; i++) {
            float xr[4];
#pragma unroll
            for (int r = 0; r < 4; r++) xr[r] = Xs[ty * 4 + r][i];
            float4 wv = *(const float4*)&Ws[i][tx * 4];
#pragma unroll
            for (int r = 0; r < 4; r++) {
                acc[r][0] += xr[r] * wv.x;
                acc[r][1] += xr[r] * wv.y;
                acc[r][2] += xr[r] * wv.z;
                acc[r][3] += xr[r] * wv.w;
            }
        }
        __syncthreads();
    }

    float bias[4] = {0.f, 0.f, 0.f, 0.f};
#pragma unroll
    for (int d = 0; d < ED; d++) {
        float e = __ldg(&E[n * ED + d]);
#pragma unroll
        for (int c = 0; c < 4; c++) bias[c] += e * __ldg(&bp[d * CC + tx * 4 + c]);
    }

#pragma unroll
    for (int r = 0; r < 4; r++) {
        int b = ty * 4 + r;
        float4 v = make_float4(acc[r][0] + bias[0], acc[r][1] + bias[1],
                               acc[r][2] + bias[2], acc[r][3] + bias[3]);
        *(float4*)&out[((size_t)b * NN + n) * CC + tx * 4] = v;
    }
}

// ---------------- launch ----------------------------------------------------
#define GEMM_SMEM 65536

extern "C" void kernel_launch(void* const* d_in, const int* in_sizes, int n_in,
                              void* d_out, int out_size)
{
    const float* x  = (const float*)d_in[0];
    const float* E  = (const float*)d_in[1];
    const float* Wp = (const float*)d_in[2];
    const float* bp = (const float*)d_in[3];
    float* out = (float*)d_out;

    float *pA, *pAT, *pT2, *pxTT, *pXg1, *pXg2;
    cudaGetSymbolAddress((void**)&pA,   g_A);
    cudaGetSymbolAddress((void**)&pAT,  g_AT);
    cudaGetSymbolAddress((void**)&pT2,  g_T2);
    cudaGetSymbolAddress((void**)&pxTT, g_xTT);
    cudaGetSymbolAddress((void**)&pXg1, g_Xg1);
    cudaGetSymbolAddress((void**)&pXg2, g_Xg2);

    static bool attr_set = false;
    if (!attr_set) {
        cudaFuncSetAttribute(gemm_mma, cudaFuncAttributeMaxDynamicSharedMemorySize, GEMM_SMEM);
        attr_set = true;
    }

    // 1. adjacency (tf32-rounded)
    supports_kernel<<<NN, 256>>>(E);
    // 2. transposes
    transposeA_kernel<<<dim3(64, 64), dim3(32, 8)>>>();
    transpose_x_kernel<<<dim3(64, 2, 64), dim3(32, 8)>>>(x);
    // 3. T2 = 2*A@A - I   (B operand = A^T), tf32-rounded output
    gemm_mma<<<dim3(NN / 128, NN / 128), 256, GEMM_SMEM>>>(pA, pAT, pT2, NN, 2.0f, 1, 1);
    // 4. Xg1 = A @ xT     (B operand = xTT)
    gemm_mma<<<dim3(BC / 128, NN / 128), 256, GEMM_SMEM>>>(pA, pxTT, pXg1, BC, 1.0f, 0, 0);
    // 5. Xg2 = T2 @ xT
    gemm_mma<<<dim3(BC / 128, NN / 128), 256, GEMM_SMEM>>>(pT2, pxTT, pXg2, BC, 1.0f, 0, 0);
    // 6. per-node weights
    weights_kernel<<<(NN * 3072) / 256, 256>>>(E, Wp);
    // 7. final contraction + bias
    final_kernel<<<NN, 256>>>(x, E, bp, out);
}

// round 5
// speedup vs baseline: 4.3215x; 1.1524x over previous
#include <cuda_runtime.h>
#include <cstdint>

// Problem constants
#define NN   2048
#define BB   64
#define CC   64
#define ED   10
#define BC   4096
#define KCH  3

// ---------------- scratch ----------------------------------------------------
__device__ float g_A   [(size_t)NN * NN];   // softmax(relu(E E^T)), tf32-rounded
__device__ float g_xTT [(size_t)BC * NN];   // xTT[b*64+c][n] = x[b][n][c], tf32-rounded
__device__ float g_xT  [(size_t)NN * BC];   // xT[n][b*64+c] = x[b][n][c], raw fp32
__device__ float g_Xg1 [(size_t)NN * BC];   // A @ xT
__device__ float g_Xg1T[(size_t)BC * NN];   // Xg1^T, tf32-rounded
__device__ float g_Xg2 [(size_t)NN * BC];   // 2 A @ Xg1 - xT
__device__ float g_W   [(size_t)NN * KCH * CC * CC];

// ---------------- helpers ------------------------------------------------
__device__ __forceinline__ uint32_t smem_u32(const void* p) {
    uint32_t a;
    asm("{ .reg .u64 t; cvta.to.shared.u64 t, %1; cvt.u32.u64 %0, t; }" : "=r"(a) : "l"(p));
    return a;
}
__device__ __forceinline__ uint32_t f2tf32(float f) {
    uint32_t r;
    asm("cvt.rna.tf32.f32 %0, %1;" : "=r"(r) : "f"(f));
    return r;
}
__device__ __forceinline__ float tf32r(float f) { return __uint_as_float(f2tf32(f)); }

__device__ __forceinline__ void cp16(uint32_t dst, const void* src) {
    asm volatile("cp.async.cg.shared.global [%0], [%1], 16;" :: "r"(dst), "l"(src) : "memory");
}
__device__ __forceinline__ void mma8(float* d, const uint32_t* a, const uint32_t* b) {
    asm volatile("mma.sync.aligned.m16n8k8.row.col.f32.tf32.tf32.f32 "
        "{%0,%1,%2,%3}, {%4,%5,%6,%7}, {%8,%9}, {%0,%1,%2,%3};"
        : "+f"(d[0]), "+f"(d[1]), "+f"(d[2]), "+f"(d[3])
        : "r"(a[0]), "r"(a[1]), "r"(a[2]), "r"(a[3]), "r"(b[0]), "r"(b[1]));
}
__device__ __forceinline__ void ldmat4(uint32_t* r, uint32_t addr) {
    asm volatile("ldmatrix.sync.aligned.m8n8.x4.shared.b16 {%0,%1,%2,%3}, [%4];"
        : "=r"(r[0]), "=r"(r[1]), "=r"(r[2]), "=r"(r[3]) : "r"(addr));
}

// ---------------- tf32 mma.sync GEMM: C = alpha * Aop @ Bop^T (- subSrc) ----
// Aop: [M,2048] row-major.  Bop: [Ncols,2048] row-major (used as B^T).
// CTA tile 128x128, warp tile 64x32, K-chunk 32, 3-stage cp.async pipeline,
// single __syncthreads per chunk, ldmatrix fragment feeds.
__global__ __launch_bounds__(256, 2)
void gemm_mma(const float* __restrict__ Aop, const float* __restrict__ Bop,
              float* __restrict__ C, int ldcN, float alpha,
              const float* __restrict__ subSrc)
{
    extern __shared__ char smem[];
    uint32_t sbase = smem_u32(smem);
    // stage s: A at s*32768, B at s*32768 + 16384

    int tid = threadIdx.x, wid = tid >> 5, lid = tid & 31;
    int m0 = blockIdx.y * 128, n0 = blockIdx.x * 128;

    // ---- loader mapping: thread -> (row ldr + 32*i, 16B k-group ldc4) ----
    int ldr = tid >> 3, ldc4 = tid & 7;
    uint32_t swz_ld = (uint32_t)(ldr * 128 + ((ldc4 * 16) ^ ((ldr & 7) * 16)));
    const float* ga = Aop + (size_t)(m0 + ldr) * NN + ldc4 * 4;
    const float* gb = Bop + (size_t)(n0 + ldr) * NN + ldc4 * 4;

#define LOAD_CHUNK(kc, buf) do { \
    int _k0 = (kc) * 32; \
    uint32_t _as = sbase + (uint32_t)(buf) * 32768u + swz_ld; \
    uint32_t _bs = _as + 16384u; \
    _Pragma("unroll") for (int i = 0; i < 4; i++) { \
        cp16(_as + (uint32_t)i * 4096u, ga + (size_t)i * 32 * NN + _k0); \
        cp16(_bs + (uint32_t)i * 4096u, gb + (size_t)i * 32 * NN + _k0); \
    } \
    asm volatile("cp.async.commit_group;" ::: "memory"); \
} while (0)

    // ---- compute mapping (2 x 4 warps of 64x32) ----
    int wm = wid & 1, wn = wid >> 1;
    int lane4 = lid & 3, lgrp = lid >> 2;
    int t7 = lid & 7;
    uint32_t swzmask = (uint32_t)(t7 * 16);

    uint32_t a_rowbase = (uint32_t)((wm * 64 + t7 + (((lid >> 3) & 1) << 3)) * 128);
    uint32_t a_khoff   = (uint32_t)(((lid >> 4) & 1) * 16);
    uint32_t b_rowbase = (uint32_t)((wn * 32 + t7 + (((lid >> 4) & 1) << 3)) * 128);
    uint32_t b_khoff   = (uint32_t)(((lid >> 3) & 1) * 16);

    float acc[4][4][4];
#pragma unroll
    for (int mt = 0; mt < 4; mt++)
#pragma unroll
        for (int nt = 0; nt < 4; nt++)
#pragma unroll
            for (int c = 0; c < 4; c++) acc[mt][nt][c] = 0.f;

    LOAD_CHUNK(0, 0);
    LOAD_CHUNK(1, 1);

    int buf = 0, nbuf = 2;   // buf = stage of chunk kc, nbuf = buffer to fill next
    for (int kc = 0; kc < 64; kc++) {
        asm volatile("cp.async.wait_group 1;" ::: "memory");
        __syncthreads();

        // issue load for chunk kc+2 into nbuf (= buffer of chunk kc-1, all done)
        if (kc + 2 < 64) LOAD_CHUNK(kc + 2, nbuf);
        else asm volatile("cp.async.commit_group;" ::: "memory");

        uint32_t ab = sbase + (uint32_t)buf * 32768u;
        uint32_t bb = ab + 16384u;
#pragma unroll
        for (int kk = 0; kk < 4; kk++) {
            uint32_t a[4][4], bfr[2][4];
            uint32_t a_k = ((uint32_t)(kk * 32) + a_khoff) ^ swzmask;
            uint32_t b_k = ((uint32_t)(kk * 32) + b_khoff) ^ swzmask;
#pragma unroll
            for (int mt = 0; mt < 4; mt++)
                ldmat4(a[mt], ab + a_rowbase + (uint32_t)(mt * 2048) + a_k);
#pragma unroll
            for (int np = 0; np < 2; np++)
                ldmat4(bfr[np], bb + b_rowbase + (uint32_t)(np * 2048) + b_k);
#pragma unroll
            for (int mt = 0; mt < 4; mt++)
#pragma unroll
                for (int nt = 0; nt < 4; nt++)
                    mma8(acc[mt][nt], a[mt], &bfr[nt >> 1][(nt & 1) * 2]);
        }
        int t = buf; buf = (buf == 2) ? 0 : buf + 1; nbuf = t;  // rotate: nbuf <- old buf
    }
#undef LOAD_CHUNK

    // epilogue (fragment layout: rows lgrp/+8, cols lane4*2)
    int row0 = m0 + wm * 64;
    int col0 = n0 + wn * 32 + lane4 * 2;
#pragma unroll
    for (int mt = 0; mt < 4; mt++) {
#pragma unroll
        for (int nt = 0; nt < 4; nt++) {
            int r = row0 + mt * 16 + lgrp;
            int c = col0 + nt * 8;
            float v0 = alpha * acc[mt][nt][0];
            float v1 = alpha * acc[mt][nt][1];
            float v2 = alpha * acc[mt][nt][2];
            float v3 = alpha * acc[mt][nt][3];
            if (subSrc) {
                float2 s0 = *(const float2*)&subSrc[(size_t)r * ldcN + c];
                float2 s1 = *(const float2*)&subSrc[(size_t)(r + 8) * ldcN + c];
                v0 -= s0.x; v1 -= s0.y; v2 -= s1.x; v3 -= s1.y;
            }
            *(float2*)&C[(size_t)r * ldcN + c]       = make_float2(v0, v1);
            *(float2*)&C[(size_t)(r + 8) * ldcN + c] = make_float2(v2, v3);
        }
    }
}

// ---------------- A = softmax(relu(E E^T)), tf32-rounded output -------------
__global__ __launch_bounds__(256) void supports_kernel(const float* __restrict__ E)
{
    int n = blockIdx.x, tid = threadIdx.x;
    float en[ED];
#pragma unroll
    for (int d = 0; d < ED; d++) en[d] = E[n * ED + d];

    float v[8], mx = 0.0f;
#pragma unroll
    for (int j = 0; j < 8; j++) {
        int m = j * 256 + tid;
        float dot = 0.f;
#pragma unroll
        for (int d = 0; d < ED; d++) dot += en[d] * __ldg(&E[m * ED + d]);
        v[j] = fmaxf(dot, 0.f);
        mx = fmaxf(mx, v[j]);
    }
    __shared__ float red[256];
    red[tid] = mx; __syncthreads();
    for (int s = 128; s > 0; s >>= 1) {
        if (tid < s) red[tid] = fmaxf(red[tid], red[tid + s]);
        __syncthreads();
    }
    mx = red[0]; __syncthreads();
    float sum = 0.f;
#pragma unroll
    for (int j = 0; j < 8; j++) { v[j] = expf(v[j] - mx); sum += v[j]; }
    red[tid] = sum; __syncthreads();
    for (int s = 128; s > 0; s >>= 1) {
        if (tid < s) red[tid] += red[tid + s];
        __syncthreads();
    }
    float inv = 1.0f / red[0];
#pragma unroll
    for (int j = 0; j < 8; j++)
        g_A[(size_t)n * NN + j * 256 + tid] = tf32r(v[j] * inv);
}

// ---------------- xTT[b*64+c][n] (tf32) and xT[n][b*64+c] (raw) -------------
__global__ __launch_bounds__(256) void transpose_x_kernel(const float* __restrict__ x)
{
    __shared__ float t[32][33];
    int tx = threadIdx.x, ty = threadIdx.y;
    int b = blockIdx.z;
    int n0 = blockIdx.x * 32, c0 = blockIdx.y * 32;
    const float* S = x + (size_t)b * NN * CC;
#pragma unroll
    for (int i = 0; i < 32; i += 8) {
        float v = S[(size_t)(n0 + ty + i) * CC + c0 + tx];
        t[ty + i][tx] = v;
        g_xT[(size_t)(n0 + ty + i) * BC + b * CC + c0 + tx] = v;
    }
    __syncthreads();
    float* D = g_xTT + (size_t)b * CC * NN;
#pragma unroll
    for (int i = 0; i < 32; i += 8)
        D[(size_t)(c0 + ty + i) * NN + n0 + tx] = tf32r(t[tx][ty + i]);
}

// ---------------- Xg1T = Xg1^T, tf32-rounded --------------------------------
__global__ __launch_bounds__(256) void transposeXg1_kernel()
{
    __shared__ float t[32][33];
    int tx = threadIdx.x, ty = threadIdx.y;
    int c0 = blockIdx.x * 32, r0 = blockIdx.y * 32;   // Xg1 is [2048 x 4096]
#pragma unroll
    for (int i = 0; i < 32; i += 8)
        t[ty + i][tx] = g_Xg1[(size_t)(r0 + ty + i) * BC + c0 + tx];
    __syncthreads();
#pragma unroll
    for (int i = 0; i < 32; i += 8)
        g_Xg1T[(size_t)(c0 + ty + i) * NN + r0 + tx] = tf32r(t[tx][ty + i]);
}

// ---------------- W[n,k,i,o] = sum_d E[n,d] Wp[d,k,i,o] ----------------------
__global__ __launch_bounds__(256) void weights_kernel(const float* __restrict__ E,
                                                      const float* __restrict__ Wp)
{
    int t = blockIdx.x * blockDim.x + threadIdx.x;
    int j4 = t % 3072;
    int n  = t / 3072;
    float4 acc = make_float4(0.f, 0.f, 0.f, 0.f);
#pragma unroll
    for (int d = 0; d < ED; d++) {
        float  e = __ldg(&E[n * ED + d]);
        float4 w = *(const float4*)&Wp[(size_t)d * 12288 + j4 * 4];
        acc.x += e * w.x; acc.y += e * w.y; acc.z += e * w.z; acc.w += e * w.w;
    }
    *(float4*)&g_W[(size_t)n * 12288 + j4 * 4] = acc;
}

// ---------------- final: out[:,n,:] = sum_k Xg_k @ W_nk + bias ---------------
__global__ __launch_bounds__(256) void final_kernel(const float* __restrict__ x,
                                                    const float* __restrict__ E,
                                                    const float* __restrict__ bp,
                                                    float* __restrict__ out)
{
    int n = blockIdx.x, tid = threadIdx.x;
    int tx = tid & 15, ty = tid >> 4;

    __shared__ float Xs[64][64];
    __shared__ float Ws[64][64];

    float acc[4][4];
#pragma unroll
    for (int r = 0; r < 4; r++)
#pragma unroll
        for (int c = 0; c < 4; c++) acc[r][c] = 0.f;

#pragma unroll
    for (int k = 0; k < KCH; k++) {
        if (k == 0) {
#pragma unroll
            for (int t = 0; t < 4; t++) {
                int e = tid + t * 256;
                int b = e >> 4, i4 = e & 15;
                *(float4*)&Xs[b][i4 * 4] =
                    *(const float4*)&x[((size_t)b * NN + n) * CC + i4 * 4];
            }
        } else {
            const float* src = (k == 1 ? g_Xg1 : g_Xg2) + (size_t)n * BC;
#pragma unroll
            for (int t = 0; t < 4; t++) {
                int e = tid + t * 256;
                ((float4*)Xs)[e] = ((const float4*)src)[e];
            }
        }
        const float* wsrc = g_W + (size_t)n * 12288 + (size_t)k * 4096;
#pragma unroll
        for (int t = 0; t < 4; t++) {
            int e = tid + t * 256;
            ((float4*)Ws)[e] = ((const float4*)wsrc)[e];
        }
        __syncthreads();

#pragma unroll 8
        for (int i = 0; i < 64; i++) {
            float xr[4];
#pragma unroll
            for (int r = 0; r < 4; r++) xr[r] = Xs[ty * 4 + r][i];
            float4 wv = *(const float4*)&Ws[i][tx * 4];
#pragma unroll
            for (int r = 0; r < 4; r++) {
                acc[r][0] += xr[r] * wv.x;
                acc[r][1] += xr[r] * wv.y;
                acc[r][2] += xr[r] * wv.z;
                acc[r][3] += xr[r] * wv.w;
            }
        }
        __syncthreads();
    }

    float bias[4] = {0.f, 0.f, 0.f, 0.f};
#pragma unroll
    for (int d = 0; d < ED; d++) {
        float e = __ldg(&E[n * ED + d]);
#pragma unroll
        for (int c = 0; c < 4; c++) bias[c] += e * __ldg(&bp[d * CC + tx * 4 + c]);
    }

#pragma unroll
    for (int r = 0; r < 4; r++) {
        int b = ty * 4 + r;
        float4 v = make_float4(acc[r][0] + bias[0], acc[r][1] + bias[1],
                               acc[r][2] + bias[2], acc[r][3] + bias[3]);
        *(float4*)&out[((size_t)b * NN + n) * CC + tx * 4] = v;
    }
}

// ---------------- launch ----------------------------------------------------
#define GEMM_SMEM 98304

extern "C" void kernel_launch(void* const* d_in, const int* in_sizes, int n_in,
                              void* d_out, int out_size)
{
    const float* x  = (const float*)d_in[0];
    const float* E  = (const float*)d_in[1];
    const float* Wp = (const float*)d_in[2];
    const float* bp = (const float*)d_in[3];
    float* out = (float*)d_out;

    float *pA, *pxTT, *pxT, *pXg1, *pXg1T, *pXg2;
    cudaGetSymbolAddress((void**)&pA,    g_A);
    cudaGetSymbolAddress((void**)&pxTT,  g_xTT);
    cudaGetSymbolAddress((void**)&pxT,   g_xT);
    cudaGetSymbolAddress((void**)&pXg1,  g_Xg1);
    cudaGetSymbolAddress((void**)&pXg1T, g_Xg1T);
    cudaGetSymbolAddress((void**)&pXg2,  g_Xg2);

    static bool attr_set = false;
    if (!attr_set) {
        cudaFuncSetAttribute(gemm_mma, cudaFuncAttributeMaxDynamicSharedMemorySize, GEMM_SMEM);
        attr_set = true;
    }

    // 1. adjacency (tf32-rounded)
    supports_kernel<<<NN, 256>>>(E);
    // 2. x transposes (xTT rounded for GEMM, xT raw for epilogue subtract)
    transpose_x_kernel<<<dim3(64, 2, 64), dim3(32, 8)>>>(x);
    // 3. Xg1 = A @ xT
    gemm_mma<<<dim3(BC / 128, NN / 128), 256, GEMM_SMEM>>>(pA, pxTT, pXg1, BC, 1.0f, nullptr);
    // 4. Xg1T (tf32-rounded)
    transposeXg1_kernel<<<dim3(128, 64), dim3(32, 8)>>>();
    // 5. Xg2 = 2 A @ Xg1 - xT   (algebraic replacement for T2 @ xT)
    gemm_mma<<<dim3(BC / 128, NN / 128), 256, GEMM_SMEM>>>(pA, pXg1T, pXg2, BC, 2.0f, pxT);
    // 6. per-node weights
    weights_kernel<<<(NN * 3072) / 256, 256>>>(E, Wp);
    // 7. final contraction + bias
    final_kernel<<<NN, 256>>>(x, E, bp, out);
}

// round 6
// speedup vs baseline: 4.6414x; 1.0740x over previous
#include <cuda_runtime.h>
#include <cstdint>

// Problem constants
#define NN   2048
#define BB   64
#define CC   64
#define ED   10
#define BC   4096
#define KCH  3

// ---------------- scratch ----------------------------------------------------
__device__ float g_A   [(size_t)NN * NN];   // softmax(relu(E E^T)), tf32-rounded
__device__ float g_xTT [(size_t)BC * NN];   // xTT[b*64+c][n] = x[b][n][c], tf32-rounded
__device__ float g_Xg1 [(size_t)NN * BC];   // A @ xT
__device__ float g_Xg1T[(size_t)BC * NN];   // Xg1^T, tf32-rounded (written by GEMM1 epilogue)
__device__ float g_Xg2p[(size_t)NN * BC];   // 2 A @ Xg1   (subtract of x happens in final2)
__device__ float g_W   [(size_t)NN * KCH * CC * CC];

// ---------------- helpers ------------------------------------------------
__device__ __forceinline__ uint32_t smem_u32(const void* p) {
    uint32_t a;
    asm("{ .reg .u64 t; cvta.to.shared.u64 t, %1; cvt.u32.u64 %0, t; }" : "=r"(a) : "l"(p));
    return a;
}
__device__ __forceinline__ uint32_t f2tf32(float f) {
    uint32_t r;
    asm("cvt.rna.tf32.f32 %0, %1;" : "=r"(r) : "f"(f));
    return r;
}
__device__ __forceinline__ float tf32r(float f) { return __uint_as_float(f2tf32(f)); }

__device__ __forceinline__ void cp16(uint32_t dst, const void* src) {
    asm volatile("cp.async.cg.shared.global [%0], [%1], 16;" :: "r"(dst), "l"(src) : "memory");
}
__device__ __forceinline__ void mma8(float* d, const uint32_t* a, const uint32_t* b) {
    asm volatile("mma.sync.aligned.m16n8k8.row.col.f32.tf32.tf32.f32 "
        "{%0,%1,%2,%3}, {%4,%5,%6,%7}, {%8,%9}, {%0,%1,%2,%3};"
        : "+f"(d[0]), "+f"(d[1]), "+f"(d[2]), "+f"(d[3])
        : "r"(a[0]), "r"(a[1]), "r"(a[2]), "r"(a[3]), "r"(b[0]), "r"(b[1]));
}
__device__ __forceinline__ void ldmat4(uint32_t* r, uint32_t addr) {
    asm volatile("ldmatrix.sync.aligned.m8n8.x4.shared.b16 {%0,%1,%2,%3}, [%4];"
        : "=r"(r[0]), "=r"(r[1]), "=r"(r[2]), "=r"(r[3]) : "r"(addr));
}

// ---------------- tf32 mma.sync GEMM: C = alpha * Aop @ Bop^T ---------------
// Aop: [M,2048] row-major.  Bop: [Ncols,2048] row-major (used as B^T).
// CTA tile 128x128, warp tile 64x32, K-chunk 32, 3-stage cp.async pipeline,
// single __syncthreads per chunk, ldmatrix fragment feeds.
// If Ct != null, also writes tf32-rounded transposed tile to Ct (ld = NN).
__global__ __launch_bounds__(256, 2)
void gemm_mma(const float* __restrict__ Aop, const float* __restrict__ Bop,
              float* __restrict__ C, int ldcN, float alpha,
              float* __restrict__ Ct)
{
    extern __shared__ char smem[];
    uint32_t sbase = smem_u32(smem);
    // stage s: A at s*32768, B at s*32768 + 16384

    int tid = threadIdx.x, wid = tid >> 5, lid = tid & 31;
    int m0 = blockIdx.y * 128, n0 = blockIdx.x * 128;

    // ---- loader mapping ----
    int ldr = tid >> 3, ldc4 = tid & 7;
    uint32_t swz_ld = (uint32_t)(ldr * 128 + ((ldc4 * 16) ^ ((ldr & 7) * 16)));
    const float* ga = Aop + (size_t)(m0 + ldr) * NN + ldc4 * 4;
    const float* gb = Bop + (size_t)(n0 + ldr) * NN + ldc4 * 4;

#define LOAD_CHUNK(kc, buf) do { \
    int _k0 = (kc) * 32; \
    uint32_t _as = sbase + (uint32_t)(buf) * 32768u + swz_ld; \
    uint32_t _bs = _as + 16384u; \
    _Pragma("unroll") for (int i = 0; i < 4; i++) { \
        cp16(_as + (uint32_t)i * 4096u, ga + (size_t)i * 32 * NN + _k0); \
        cp16(_bs + (uint32_t)i * 4096u, gb + (size_t)i * 32 * NN + _k0); \
    } \
    asm volatile("cp.async.commit_group;" ::: "memory"); \
} while (0)

    // ---- compute mapping (2 x 4 warps of 64x32) ----
    int wm = wid & 1, wn = wid >> 1;
    int lane4 = lid & 3, lgrp = lid >> 2;
    int t7 = lid & 7;
    uint32_t swzmask = (uint32_t)(t7 * 16);

    uint32_t a_rowbase = (uint32_t)((wm * 64 + t7 + (((lid >> 3) & 1) << 3)) * 128);
    uint32_t a_khoff   = (uint32_t)(((lid >> 4) & 1) * 16);
    uint32_t b_rowbase = (uint32_t)((wn * 32 + t7 + (((lid >> 4) & 1) << 3)) * 128);
    uint32_t b_khoff   = (uint32_t)(((lid >> 3) & 1) * 16);

    float acc[4][4][4];
#pragma unroll
    for (int mt = 0; mt < 4; mt++)
#pragma unroll
        for (int nt = 0; nt < 4; nt++)
#pragma unroll
            for (int c = 0; c < 4; c++) acc[mt][nt][c] = 0.f;

    LOAD_CHUNK(0, 0);
    LOAD_CHUNK(1, 1);

    int buf = 0, nbuf = 2;
    for (int kc = 0; kc < 64; kc++) {
        asm volatile("cp.async.wait_group 1;" ::: "memory");
        __syncthreads();

        if (kc + 2 < 64) LOAD_CHUNK(kc + 2, nbuf);
        else asm volatile("cp.async.commit_group;" ::: "memory");

        uint32_t ab = sbase + (uint32_t)buf * 32768u;
        uint32_t bb = ab + 16384u;
#pragma unroll
        for (int kk = 0; kk < 4; kk++) {
            uint32_t a[4][4], bfr[2][4];
            uint32_t a_k = ((uint32_t)(kk * 32) + a_khoff) ^ swzmask;
            uint32_t b_k = ((uint32_t)(kk * 32) + b_khoff) ^ swzmask;
#pragma unroll
            for (int mt = 0; mt < 4; mt++)
                ldmat4(a[mt], ab + a_rowbase + (uint32_t)(mt * 2048) + a_k);
#pragma unroll
            for (int np = 0; np < 2; np++)
                ldmat4(bfr[np], bb + b_rowbase + (uint32_t)(np * 2048) + b_k);
#pragma unroll
            for (int mt = 0; mt < 4; mt++)
#pragma unroll
                for (int nt = 0; nt < 4; nt++)
                    mma8(acc[mt][nt], a[mt], &bfr[nt >> 1][(nt & 1) * 2]);
        }
        int t = buf; buf = (buf == 2) ? 0 : buf + 1; nbuf = t;
    }
#undef LOAD_CHUNK

    // ---- epilogue ----
    __syncthreads();   // all mainloop smem reads done before staging reuse
    float* st = (float*)smem;  // 128 x 128 staging, stride 129 (66 KB)

    int row0 = m0 + wm * 64;
    int col0 = n0 + wn * 32 + lane4 * 2;
    int lr0  = wm * 64;              // local row/col within tile
    int lc0  = wn * 32 + lane4 * 2;
#pragma unroll
    for (int mt = 0; mt < 4; mt++) {
#pragma unroll
        for (int nt = 0; nt < 4; nt++) {
            int r = row0 + mt * 16 + lgrp;
            int c = col0 + nt * 8;
            float v0 = alpha * acc[mt][nt][0];
            float v1 = alpha * acc[mt][nt][1];
            float v2 = alpha * acc[mt][nt][2];
            float v3 = alpha * acc[mt][nt][3];
            *(float2*)&C[(size_t)r * ldcN + c]       = make_float2(v0, v1);
            *(float2*)&C[(size_t)(r + 8) * ldcN + c] = make_float2(v2, v3);
            if (Ct) {
                int lr = lr0 + mt * 16 + lgrp;
                int lc = lc0 + nt * 8;
                st[lr * 129 + lc]           = v0;
                st[lr * 129 + lc + 1]       = v1;
                st[(lr + 8) * 129 + lc]     = v2;
                st[(lr + 8) * 129 + lc + 1] = v3;
            }
        }
    }
    if (Ct) {
        __syncthreads();
        // transposed write: Ct[(n0+c)][m0+r], coalesced over r
        for (int i = tid; i < 16384; i += 256) {
            int c = i >> 7, r = i & 127;
            Ct[(size_t)(n0 + c) * NN + m0 + r] = tf32r(st[r * 129 + c]);
        }
    }
}

// ---------------- A = softmax(relu(E E^T)), tf32-rounded output -------------
__global__ __launch_bounds__(256) void supports_kernel(const float* __restrict__ E)
{
    int n = blockIdx.x, tid = threadIdx.x;
    float en[ED];
#pragma unroll
    for (int d = 0; d < ED; d++) en[d] = E[n * ED + d];

    float v[8], mx = 0.0f;
#pragma unroll
    for (int j = 0; j < 8; j++) {
        int m = j * 256 + tid;
        float dot = 0.f;
#pragma unroll
        for (int d = 0; d < ED; d++) dot += en[d] * __ldg(&E[m * ED + d]);
        v[j] = fmaxf(dot, 0.f);
        mx = fmaxf(mx, v[j]);
    }
    __shared__ float red[256];
    red[tid] = mx; __syncthreads();
    for (int s = 128; s > 0; s >>= 1) {
        if (tid < s) red[tid] = fmaxf(red[tid], red[tid + s]);
        __syncthreads();
    }
    mx = red[0]; __syncthreads();
    float sum = 0.f;
#pragma unroll
    for (int j = 0; j < 8; j++) { v[j] = expf(v[j] - mx); sum += v[j]; }
    red[tid] = sum; __syncthreads();
    for (int s = 128; s > 0; s >>= 1) {
        if (tid < s) red[tid] += red[tid + s];
        __syncthreads();
    }
    float inv = 1.0f / red[0];
#pragma unroll
    for (int j = 0; j < 8; j++)
        g_A[(size_t)n * NN + j * 256 + tid] = tf32r(v[j] * inv);
}

// ---------------- xTT[b*64+c][n] = x[b][n][c], tf32-rounded ------------------
__global__ __launch_bounds__(256) void transpose_x_kernel(const float* __restrict__ x)
{
    __shared__ float t[32][33];
    int tx = threadIdx.x, ty = threadIdx.y;
    int b = blockIdx.z;
    int n0 = blockIdx.x * 32, c0 = blockIdx.y * 32;
    const float* S = x + (size_t)b * NN * CC;
#pragma unroll
    for (int i = 0; i < 32; i += 8)
        t[ty + i][tx] = S[(size_t)(n0 + ty + i) * CC + c0 + tx];
    __syncthreads();
    float* D = g_xTT + (size_t)b * CC * NN;
#pragma unroll
    for (int i = 0; i < 32; i += 8)
        D[(size_t)(c0 + ty + i) * NN + n0 + tx] = tf32r(t[tx][ty + i]);
}

// ---------------- W[n,k,i,o] = sum_d E[n,d] Wp[d,k,i,o] ----------------------
__global__ __launch_bounds__(256) void weights_kernel(const float* __restrict__ E,
                                                      const float* __restrict__ Wp)
{
    int t = blockIdx.x * blockDim.x + threadIdx.x;
    int j4 = t % 3072;
    int n  = t / 3072;
    float4 acc = make_float4(0.f, 0.f, 0.f, 0.f);
#pragma unroll
    for (int d = 0; d < ED; d++) {
        float  e = __ldg(&E[n * ED + d]);
        float4 w = *(const float4*)&Wp[(size_t)d * 12288 + j4 * 4];
        acc.x += e * w.x; acc.y += e * w.y; acc.z += e * w.z; acc.w += e * w.w;
    }
    *(float4*)&g_W[(size_t)n * 12288 + j4 * 4] = acc;
}

// ---------------- final01: out[:,n,:] = x@W0 + Xg1@W1 + bias -----------------
__global__ __launch_bounds__(256) void final01_kernel(const float* __restrict__ x,
                                                      const float* __restrict__ E,
                                                      const float* __restrict__ bp,
                                                      float* __restrict__ out)
{
    int n = blockIdx.x, tid = threadIdx.x;
    int tx = tid & 15, ty = tid >> 4;

    __shared__ float Xs[64][64];
    __shared__ float Ws[64][64];

    float acc[4][4];
#pragma unroll
    for (int r = 0; r < 4; r++)
#pragma unroll
        for (int c = 0; c < 4; c++) acc[r][c] = 0.f;

#pragma unroll
    for (int k = 0; k < 2; k++) {
        if (k == 0) {
#pragma unroll
            for (int t = 0; t < 4; t++) {
                int e = tid + t * 256;
                int b = e >> 4, i4 = e & 15;
                *(float4*)&Xs[b][i4 * 4] =
                    *(const float4*)&x[((size_t)b * NN + n) * CC + i4 * 4];
            }
        } else {
            const float* src = g_Xg1 + (size_t)n * BC;
#pragma unroll
            for (int t = 0; t < 4; t++) {
                int e = tid + t * 256;
                ((float4*)Xs)[e] = ((const float4*)src)[e];
            }
        }
        const float* wsrc = g_W + (size_t)n * 12288 + (size_t)k * 4096;
#pragma unroll
        for (int t = 0; t < 4; t++) {
            int e = tid + t * 256;
            ((float4*)Ws)[e] = ((const float4*)wsrc)[e];
        }
        __syncthreads();

#pragma unroll 8
        for (int i = 0; i < 64; i++) {
            float xr[4];
#pragma unroll
            for (int r = 0; r < 4; r++) xr[r] = Xs[ty * 4 + r][i];
            float4 wv = *(const float4*)&Ws[i][tx * 4];
#pragma unroll
            for (int r = 0; r < 4; r++) {
                acc[r][0] += xr[r] * wv.x;
                acc[r][1] += xr[r] * wv.y;
                acc[r][2] += xr[r] * wv.z;
                acc[r][3] += xr[r] * wv.w;
            }
        }
        __syncthreads();
    }

    float bias[4] = {0.f, 0.f, 0.f, 0.f};
#pragma unroll
    for (int d = 0; d < ED; d++) {
        float e = __ldg(&E[n * ED + d]);
#pragma unroll
        for (int c = 0; c < 4; c++) bias[c] += e * __ldg(&bp[d * CC + tx * 4 + c]);
    }

#pragma unroll
    for (int r = 0; r < 4; r++) {
        int b = ty * 4 + r;
        float4 v = make_float4(acc[r][0] + bias[0], acc[r][1] + bias[1],
                               acc[r][2] + bias[2], acc[r][3] + bias[3]);
        *(float4*)&out[((size_t)b * NN + n) * CC + tx * 4] = v;
    }
}

// ---------------- final2: out += (Xg2p - xT) @ W2 ----------------------------
__global__ __launch_bounds__(256) void final2_kernel(const float* __restrict__ x,
                                                     float* __restrict__ out)
{
    int n = blockIdx.x, tid = threadIdx.x;
    int tx = tid & 15, ty = tid >> 4;

    __shared__ float Xs[64][64];
    __shared__ float Ws[64][64];

    const float* src = g_Xg2p + (size_t)n * BC;
#pragma unroll
    for (int t = 0; t < 4; t++) {
        int e = tid + t * 256;
        int b = e >> 4, i4 = e & 15;
        float4 g = ((const float4*)src)[e];
        float4 xv = *(const float4*)&x[((size_t)b * NN + n) * CC + i4 * 4];
        g.x -= xv.x; g.y -= xv.y; g.z -= xv.z; g.w -= xv.w;
        ((float4*)Xs)[e] = g;
    }
    const float* wsrc = g_W + (size_t)n * 12288 + (size_t)2 * 4096;
#pragma unroll
    for (int t = 0; t < 4; t++) {
        int e = tid + t * 256;
        ((float4*)Ws)[e] = ((const float4*)wsrc)[e];
    }
    __syncthreads();

    float acc[4][4];
#pragma unroll
    for (int r = 0; r < 4; r++)
#pragma unroll
        for (int c = 0; c < 4; c++) acc[r][c] = 0.f;

#pragma unroll 8
    for (int i = 0; i < 64; i++) {
        float xr[4];
#pragma unroll
        for (int r = 0; r < 4; r++) xr[r] = Xs[ty * 4 + r][i];
        float4 wv = *(const float4*)&Ws[i][tx * 4];
#pragma unroll
        for (int r = 0; r < 4; r++) {
            acc[r][0] += xr[r] * wv.x;
            acc[r][1] += xr[r] * wv.y;
            acc[r][2] += xr[r] * wv.z;
            acc[r][3] += xr[r] * wv.w;
        }
    }

#pragma unroll
    for (int r = 0; r < 4; r++) {
        int b = ty * 4 + r;
        float4 v = *(float4*)&out[((size_t)b * NN + n) * CC + tx * 4];
        v.x += acc[r][0]; v.y += acc[r][1]; v.z += acc[r][2]; v.w += acc[r][3];
        *(float4*)&out[((size_t)b * NN + n) * CC + tx * 4] = v;
    }
}

// ---------------- launch ----------------------------------------------------
#define GEMM_SMEM 98304

extern "C" void kernel_launch(void* const* d_in, const int* in_sizes, int n_in,
                              void* d_out, int out_size)
{
    const float* x  = (const float*)d_in[0];
    const float* E  = (const float*)d_in[1];
    const float* Wp = (const float*)d_in[2];
    const float* bp = (const float*)d_in[3];
    float* out = (float*)d_out;

    float *pA, *pxTT, *pXg1, *pXg1T, *pXg2p;
    cudaGetSymbolAddress((void**)&pA,    g_A);
    cudaGetSymbolAddress((void**)&pxTT,  g_xTT);
    cudaGetSymbolAddress((void**)&pXg1,  g_Xg1);
    cudaGetSymbolAddress((void**)&pXg1T, g_Xg1T);
    cudaGetSymbolAddress((void**)&pXg2p, g_Xg2p);

    static bool init_done = false;
    static cudaStream_t s1, s2;
    static cudaEvent_t e0, e1, e2, e3;
    if (!init_done) {
        cudaFuncSetAttribute(gemm_mma, cudaFuncAttributeMaxDynamicSharedMemorySize, GEMM_SMEM);
        cudaStreamCreateWithFlags(&s1, cudaStreamNonBlocking);
        cudaStreamCreateWithFlags(&s2, cudaStreamNonBlocking);
        cudaEventCreateWithFlags(&e0, cudaEventDisableTiming);
        cudaEventCreateWithFlags(&e1, cudaEventDisableTiming);
        cudaEventCreateWithFlags(&e2, cudaEventDisableTiming);
        cudaEventCreateWithFlags(&e3, cudaEventDisableTiming);
        init_done = true;
    }

    // fork side streams from the capture-origin (default) stream
    cudaEventRecord(e0, 0);
    cudaStreamWaitEvent(s1, e0, 0);
    cudaStreamWaitEvent(s2, e0, 0);

    // s1: x transpose (tf32)          — needed by GEMM1
    transpose_x_kernel<<<dim3(64, 2, 64), dim3(32, 8), 0, s1>>>(x);
    // s2: per-node weights            — needed by final01
    weights_kernel<<<(NN * 3072) / 256, 256, 0, s2>>>(E, Wp);
    // main: adjacency                 — needed by GEMM1
    supports_kernel<<<NN, 256>>>(E);

    // join s1 before GEMM1
    cudaEventRecord(e1, s1);
    cudaStreamWaitEvent(0, e1, 0);

    // GEMM1: Xg1 = A @ xT  (+ fused tf32 transposed copy Xg1T)
    gemm_mma<<<dim3(BC / 128, NN / 128), 256, GEMM_SMEM>>>(pA, pxTT, pXg1, BC, 1.0f, pXg1T);

    // final01 on s2 (needs Xg1 + W): overlaps GEMM2
    cudaEventRecord(e2, 0);
    cudaStreamWaitEvent(s2, e2, 0);
    final01_kernel<<<NN, 256, 0, s2>>>(x, E, bp, out);

    // GEMM2 on main: Xg2p = 2 A @ Xg1
    gemm_mma<<<dim3(BC / 128, NN / 128), 256, GEMM_SMEM>>>(pA, pXg1T, pXg2p, BC, 2.0f, nullptr);

    // join s2, then final accumulation
    cudaEventRecord(e3, s2);
    cudaStreamWaitEvent(0, e3, 0);
    final2_kernel<<<NN, 256>>>(x, out);
}